// round 6
// baseline (speedup 1.0000x reference)
#include <cuda_runtime.h>
#include <math.h>

#define BB 8
#define QQ 1024
#define KN 1024
#define CC 16
#define OUTD 32
#define HH 16
#define WINDOW 0.25f
#define NTAB 3072
#define CHB 4            // channels per main-kernel block
#define QTHREADS 256
#define TBLK (NTAB / 256)   // 12 table blocks per channel

// -------- device scratch (no allocations allowed) --------
__device__ float2 g_tab2[CC][NTAB];          // duplicated pairs (t[i], t[i+1])
__device__ float  g_pos[BB][KN];             // keys sorted by channel
__device__ float  g_val[BB][KN];             // values[b,k,ch_k] sorted by channel
__device__ int    g_seg[BB][CC + 1];         // channel segment offsets
__device__ float  g_td[BB * QQ * 2 * CC];    // [targets(16) | dens(16)] per (b,q)

// ------------------------------------------------------------
// scalar MLP:  w(a, ch) = |MLP([a, onehot(ch)])|
// ------------------------------------------------------------
__device__ __forceinline__ float mlp_eval(float a, int ch,
    const float* __restrict__ W0, const float* __restrict__ b0,
    const float* __restrict__ W1, const float* __restrict__ b1,
    const float* __restrict__ W2, const float* __restrict__ b2,
    const float* __restrict__ W3, const float* __restrict__ b3) {
    float h0[HH], h1[HH];
#pragma unroll
    for (int j = 0; j < HH; j++) {
        float v = a * W0[j * (CC + 1)] + W0[j * (CC + 1) + 1 + ch] + b0[j];
        h0[j] = v > 0.0f ? v : 0.0f;
    }
#pragma unroll
    for (int j = 0; j < HH; j++) {
        float s = b1[j];
#pragma unroll
        for (int l = 0; l < HH; l++) s = fmaf(W1[j * HH + l], h0[l], s);
        h1[j] = s > 0.0f ? s : 0.0f;
    }
#pragma unroll
    for (int j = 0; j < HH; j++) {
        float s = b2[j];
#pragma unroll
        for (int l = 0; l < HH; l++) s = fmaf(W2[j * HH + l], h1[l], s);
        h0[j] = s > 0.0f ? s : 0.0f;   // reuse h0 as h2
    }
    float s = b3[0];
#pragma unroll
    for (int l = 0; l < HH; l++) s = fmaf(W3[l], h0[l], s);
    return fabsf(s);
}

// ============================================================
// Kernel 1 (prep): blocks [0, TBLK*CC) tabulate the MLP as
// float2 pairs; blocks [TBLK*CC, +BB) counting-sort keys.
// ============================================================
__global__ void prep_kernel(const float* __restrict__ keys_in,
                            const float* __restrict__ values,
                            const float* __restrict__ W0, const float* __restrict__ b0,
                            const float* __restrict__ W1, const float* __restrict__ b1,
                            const float* __restrict__ W2, const float* __restrict__ b2,
                            const float* __restrict__ W3, const float* __restrict__ b3) {
    int bx  = blockIdx.x;
    int tid = threadIdx.x;

    if (bx < TBLK * CC) {
        // ---- table build: 256 samples + boundary, write duplicated pairs ----
        __shared__ float s[257];
        int ch   = bx / TBLK;
        int base = (bx % TBLK) * 256;
        const float STEP = WINDOW / (float)NTAB;
        s[tid] = mlp_eval((float)(base + tid) * STEP, ch,
                          W0, b0, W1, b1, W2, b2, W3, b3);
        if (tid == 0)
            s[256] = mlp_eval((float)(base + 256) * STEP, ch,
                              W0, b0, W1, b1, W2, b2, W3, b3);
        __syncthreads();
        g_tab2[ch][base + tid] = make_float2(s[tid], s[tid + 1]);
    } else {
        // ---- counting sort by channel for batch b ----
        int b = bx - TBLK * CC;
        __shared__ int cnt[CC];
        __shared__ int cur[CC];
        if (tid < CC) cnt[tid] = 0;
        __syncthreads();
        for (int k = tid; k < KN; k += blockDim.x) {
            int ch = (int)keys_in[(b * KN + k) * 2];
            atomicAdd(&cnt[ch], 1);
        }
        __syncthreads();
        if (tid == 0) {
            int acc = 0;
            for (int c = 0; c < CC; c++) {
                g_seg[b][c] = acc;
                cur[c] = acc;
                acc += cnt[c];
            }
            g_seg[b][CC] = acc;
        }
        __syncthreads();
        for (int k = tid; k < KN; k += blockDim.x) {
            int   ch  = (int)keys_in[(b * KN + k) * 2];
            float pos = keys_in[(b * KN + k) * 2 + 1];
            int r = atomicAdd(&cur[ch], 1);
            g_pos[b][r] = pos;
            g_val[b][r] = values[(b * KN + k) * CC + ch];
        }
    }
}

// ============================================================
// Kernel 2: main pairwise accumulation via table lookup
// grid = (Q/256, 16/CHB, B), block = 256, thread = one query
// ============================================================
__global__ void main_kernel(const float* __restrict__ queries,
                            const float* __restrict__ Wd,
                            const float* __restrict__ bd) {
    extern __shared__ float2 sm[];
    float2* stab = sm;                 // CHB * NTAB duplicated pairs
    float2* skey = sm + CHB * NTAB;    // (pos, val) for this channel chunk

    int tid = threadIdx.x;
    int b   = blockIdx.z;
    int c0  = blockIdx.y * CHB;
    int q0  = blockIdx.x * QTHREADS;

    int soff[CHB + 1];
#pragma unroll
    for (int i = 0; i <= CHB; i++) soff[i] = g_seg[b][c0 + i];
    int s0  = soff[0];
    int len = soff[CHB] - s0;

    // stage table chunk into smem (one 8B load per entry)
#pragma unroll
    for (int cl = 0; cl < CHB; cl++) {
        const float2* tb = g_tab2[c0 + cl];
        for (int i = tid; i < NTAB; i += QTHREADS)
            stab[cl * NTAB + i] = tb[i];
    }
    // stage keys of this chunk
    for (int k = tid; k < len; k += QTHREADS)
        skey[k] = make_float2(g_pos[b][s0 + k], g_val[b][s0 + k]);
    __syncthreads();

    float qv  = queries[b * QQ + q0 + tid];
    float wdv = Wd[0];
    float bdv = bd[0];
    const float SCALE = (float)NTAB / WINDOW;
    int qi = (b * QQ + q0 + tid) * (2 * CC);

#pragma unroll
    for (int cl = 0; cl < CHB; cl++) {
        int kb = soff[cl] - s0;
        int ke = soff[cl + 1] - s0;
        const float2* tb = stab + cl * NTAB;
        float den = 0.0f, num = 0.0f;
#pragma unroll 4
        for (int k = kb; k < ke; k++) {
            float2 kv = skey[k];                 // warp-uniform broadcast LDS
            float ad = fabsf(kv.x - qv);         // identical to ref's |pos - q|
            if (ad < WINDOW) {                   // identical strict mask
                float t  = ad * SCALE;
                int   i  = (int)t;
                float fr = t - (float)i;
                float2 tt = tb[i];               // one LDS.64
                float w = fmaf(tt.y - tt.x, fr, tt.x);
                den += w;
                num = fmaf(w, kv.y, num);
            }
        }
        float target = num / (den + 1e-5f);
        float x  = (den * 0.1f - 1.0f) * wdv + bdv;
        float dn = 1.0f / (1.0f + expf(-x));
        g_td[qi + c0 + cl]      = target;
        g_td[qi + CC + c0 + cl] = dn;
    }
}

// ============================================================
// Kernel 3: epilogue  out = [targets | dens] @ Wr^T + br
// block = 256 threads = 8 queries x 32 outputs; grid = B*Q/8
// ============================================================
__global__ void epilogue_kernel(const float* __restrict__ Wr,
                                const float* __restrict__ br,
                                float* __restrict__ out) {
    __shared__ float sWrT[2 * CC][OUTD];   // transposed: sWrT[i][o] = Wr[o][i]
    __shared__ float sbr[OUTD];
    __shared__ float scat[8][2 * CC];
    int tid = threadIdx.x;

    // stage ALL of Wr transposed: 1024 elements, 256 threads -> 4 each
#pragma unroll
    for (int e = tid; e < OUTD * 2 * CC; e += 256) {
        int o = e / (2 * CC);
        int i = e % (2 * CC);
        sWrT[i][o] = Wr[e];
    }
    if (tid < OUTD) sbr[tid] = br[tid];

    int q0 = blockIdx.x * 8;               // flat (b,q) base
    // stage 8 query cat rows, coalesced (256 floats)
    scat[tid >> 5][tid & 31] = g_td[q0 * (2 * CC) + tid];
    __syncthreads();

    int ql = tid >> 5;                     // warp = one query
    int o  = tid & 31;                     // lane = one output
    float acc = sbr[o];
#pragma unroll
    for (int i = 0; i < 2 * CC; i++)
        acc = fmaf(sWrT[i][o], scat[ql][i], acc);   // conflict-free + broadcast
    out[(q0 + ql) * OUTD + o] = acc;
}

// ============================================================
extern "C" void kernel_launch(void* const* d_in, const int* in_sizes, int n_in,
                              void* d_out, int out_size) {
    const float* keys_in = (const float*)d_in[0];
    const float* queries = (const float*)d_in[1];
    const float* values  = (const float*)d_in[2];
    const float* W0 = (const float*)d_in[3];
    const float* b0 = (const float*)d_in[4];
    const float* W1 = (const float*)d_in[5];
    const float* b1 = (const float*)d_in[6];
    const float* W2 = (const float*)d_in[7];
    const float* b2 = (const float*)d_in[8];
    const float* W3 = (const float*)d_in[9];
    const float* b3 = (const float*)d_in[10];
    const float* Wd = (const float*)d_in[11];
    const float* bd = (const float*)d_in[12];
    const float* Wr = (const float*)d_in[13];
    const float* br = (const float*)d_in[14];
    float* out = (float*)d_out;

    const size_t main_smem = (size_t)(CHB * NTAB) * sizeof(float2)
                           + (size_t)KN * sizeof(float2);
    cudaFuncSetAttribute(main_kernel, cudaFuncAttributeMaxDynamicSharedMemorySize,
                         (int)main_smem);

    prep_kernel<<<TBLK * CC + BB, 256>>>(keys_in, values,
                                         W0, b0, W1, b1, W2, b2, W3, b3);

    dim3 mgrid(QQ / QTHREADS, CC / CHB, BB);
    main_kernel<<<mgrid, QTHREADS, main_smem>>>(queries, Wd, bd);

    epilogue_kernel<<<BB * QQ / 8, 256>>>(Wr, br, out);
}